// round 15
// baseline (speedup 1.0000x reference)
#include <cuda_runtime.h>
#include <math.h>
#include <stdint.h>

// ---------------------------------------------------------------------------
// Shapes (fixed)
// ---------------------------------------------------------------------------
#define Hd 1024
#define Fd 4096
#define Ed 8
#define Td 512
#define OUT_TOK 2048

// ---------------------------------------------------------------------------
// Static device scratch (allocation-free; uint4 arrays for 16B alignment)
// ---------------------------------------------------------------------------
__device__ uint4 g_qA1hi[(size_t)Ed * Td * Hd / 16];   // dispatch A planes (int8)
__device__ uint4 g_qA1lo[(size_t)Ed * Td * Hd / 16];
__device__ uint4 g_qA2hi[(size_t)Ed * Td * Fd / 16];   // hmid A planes (int8)
__device__ uint4 g_qA2lo[(size_t)Ed * Td * Fd / 16];
__device__ uint4 g_W1q_hi[(size_t)Ed * Fd * Hd / 16];  // W1^T planes [e][n][k] int8
__device__ uint4 g_W1q_lo[(size_t)Ed * Fd * Hd / 16];
__device__ uint4 g_W2q_hi[(size_t)Ed * Hd * Fd / 16];  // W2^T planes [e][h][f] int8
__device__ uint4 g_W2q_lo[(size_t)Ed * Hd * Fd / 16];
__device__ float g_sA1[Ed * Td];                       // A row scales (GEMM1)
__device__ float g_sA2[Ed * Td];                       // A row scales (GEMM2)
__device__ float g_sB1[Ed * Fd];                       // B col scales (W1)
__device__ float g_sB2[Ed * Hd];                       // B col scales (W2)
__device__ float g_hmid[(size_t)Ed * Td * Fd];         // GEMM1+GELU out (fp32)
__device__ float g_obuf[Ed * Td * Hd];                 // GEMM2 out (fp32)
__device__ int   g_order[Td][Ed];
__device__ float g_score[Td][Ed];

// ---------------------------------------------------------------------------
// Helpers
// ---------------------------------------------------------------------------
__device__ __forceinline__ uint32_t smem_u32(const void* p) {
    uint32_t a;
    asm("{ .reg .u64 t; cvta.to.shared.u64 t, %1; cvt.u32.u64 %0, t; }" : "=r"(a) : "l"(p));
    return a;
}
__device__ __forceinline__ void cp_async16(uint32_t saddr, const void* gaddr) {
    asm volatile("cp.async.cg.shared.global [%0], [%1], 16;" :: "r"(saddr), "l"(gaddr));
}
__device__ __forceinline__ void cp_commit() {
    asm volatile("cp.async.commit_group;" ::: "memory");
}
__device__ __forceinline__ void cp_wait1() {
    asm volatile("cp.async.wait_group 1;" ::: "memory");
}
__device__ __forceinline__ void ldsm_x4(uint32_t& r0, uint32_t& r1, uint32_t& r2,
                                        uint32_t& r3, uint32_t addr) {
    asm volatile("ldmatrix.sync.aligned.m8n8.x4.shared.b16 {%0,%1,%2,%3}, [%4];"
                 : "=r"(r0), "=r"(r1), "=r"(r2), "=r"(r3) : "r"(addr));
}
__device__ __forceinline__ void imma(int c[4], uint32_t a0, uint32_t a1,
                                     uint32_t a2, uint32_t a3,
                                     uint32_t b0, uint32_t b1) {
    asm volatile(
        "mma.sync.aligned.m16n8k32.row.col.s32.s8.s8.s32 "
        "{%0,%1,%2,%3}, {%4,%5,%6,%7}, {%8,%9}, {%0,%1,%2,%3};"
        : "+r"(c[0]), "+r"(c[1]), "+r"(c[2]), "+r"(c[3])
        : "r"(a0), "r"(a1), "r"(a2), "r"(a3), "r"(b0), "r"(b1));
}
__device__ __forceinline__ float gelu_exact(float v) {
    return 0.5f * v * (1.0f + erff(v * 0.70710678118654752f));
}
__device__ __forceinline__ uint32_t pack4(int a, int b, int c, int d) {
    return (uint32_t)(a & 0xff) | ((uint32_t)(b & 0xff) << 8) |
           ((uint32_t)(c & 0xff) << 16) | ((uint32_t)(d & 0xff) << 24);
}
// split a 15-bit quantized value into (hi, lo): q = 128*hi + lo
__device__ __forceinline__ void qsplit(float v, float inv, int& hi, int& lo) {
    float qa = fminf(fmaxf(rintf(v * inv), -16256.f), 16256.f);
    hi = (int)rintf(qa * (1.0f / 128.0f));
    lo = (int)qa - 128 * hi;
}

// ---------------------------------------------------------------------------
// Gating (unchanged)
// ---------------------------------------------------------------------------
__global__ void gate_kernel(const float* __restrict__ x,
                            const float* __restrict__ Wg,
                            const float* __restrict__ bg) {
    int warp = threadIdx.x >> 5;
    int lane = threadIdx.x & 31;
    int t = blockIdx.x * 8 + warp;
    if (t >= Td) return;

    const float* xr = x + (size_t)t * Hd;
    float acc[Ed];
#pragma unroll
    for (int e = 0; e < Ed; e++) acc[e] = 0.f;
    for (int h = lane; h < Hd; h += 32) {
        float xv = xr[h];
        const float* wr = Wg + (size_t)h * Ed;
#pragma unroll
        for (int e = 0; e < Ed; e++) acc[e] += xv * wr[e];
    }
#pragma unroll
    for (int e = 0; e < Ed; e++) {
#pragma unroll
        for (int o = 16; o > 0; o >>= 1)
            acc[e] += __shfl_xor_sync(0xffffffffu, acc[e], o);
    }
    if (lane == 0) {
        float l[Ed], p[Ed];
        float mx = -1e30f;
#pragma unroll
        for (int e = 0; e < Ed; e++) { l[e] = acc[e] + bg[e]; mx = fmaxf(mx, l[e]); }
        float s = 0.f;
#pragma unroll
        for (int e = 0; e < Ed; e++) { p[e] = expf(l[e] - mx); s += p[e]; }
#pragma unroll
        for (int e = 0; e < Ed; e++) p[e] /= s;
        float sum = 0.f;
#pragma unroll
        for (int e = 0; e < Ed; e++) sum += p[e];
        float inv = 1.0f / (sum + 1e-9f);
        bool used[Ed];
#pragma unroll
        for (int e = 0; e < Ed; e++) used[e] = false;
        for (int r = 0; r < Ed; r++) {
            int best = -1; float bv = -1e30f;
            for (int e = 0; e < Ed; e++)
                if (!used[e] && p[e] > bv) { bv = p[e]; best = e; }
            used[best] = true;
            g_order[t][r] = best;
            g_score[t][r] = bv * inv;
        }
    }
}

// ---------------------------------------------------------------------------
// Dispatch + int8 quantize: one block per (t, r); exact per-row max.
// ---------------------------------------------------------------------------
__global__ void dispatch_kernel(const float* __restrict__ x) {
    int t = blockIdx.x;
    int r = blockIdx.y;
    int e = g_order[t][r];
    float sc = g_score[t][r];
    int src = 4 * t + (r >> 1);
    const float4* xs = (const float4*)(x + (size_t)src * Hd);
    int tid = threadIdx.x;

    float4 v = xs[tid];
    v.x *= sc; v.y *= sc; v.z *= sc; v.w *= sc;

    __shared__ float red[256];
    float m = fmaxf(fmaxf(fabsf(v.x), fabsf(v.y)), fmaxf(fabsf(v.z), fabsf(v.w)));
    red[tid] = m; __syncthreads();
    for (int s = 128; s > 0; s >>= 1) {
        if (tid < s) red[tid] = fmaxf(red[tid], red[tid + s]);
        __syncthreads();
    }
    float mx = red[0];
    float inv = (mx > 0.f) ? 16256.0f / mx : 0.0f;

    int h0, l0, h1, l1, h2, l2, h3, l3;
    qsplit(v.x, inv, h0, l0); qsplit(v.y, inv, h1, l1);
    qsplit(v.z, inv, h2, l2); qsplit(v.w, inv, h3, l3);

    uint32_t* qh = (uint32_t*)g_qA1hi;
    uint32_t* ql = (uint32_t*)g_qA1lo;
    size_t base = ((size_t)e * Td + t) * (Hd / 4);
    qh[base + tid] = pack4(h0, h1, h2, h3);
    ql[base + tid] = pack4(l0, l1, l2, l3);
    if (tid == 0) g_sA1[e * Td + t] = mx * (1.0f / 16256.0f);
}

// ---------------------------------------------------------------------------
// hmid quantize: one block per row (E*Td rows of Fd floats)
// ---------------------------------------------------------------------------
__global__ void hquant_kernel() {
    int row = blockIdx.x;
    int tid = threadIdx.x;
    const float4* src = (const float4*)(g_hmid + (size_t)row * Fd);

    float4 v[4];
#pragma unroll
    for (int j = 0; j < 4; j++) v[j] = src[tid + 256 * j];

    __shared__ float red[256];
    float m = 0.f;
#pragma unroll
    for (int j = 0; j < 4; j++)
        m = fmaxf(m, fmaxf(fmaxf(fabsf(v[j].x), fabsf(v[j].y)),
                           fmaxf(fabsf(v[j].z), fabsf(v[j].w))));
    red[tid] = m; __syncthreads();
    for (int s = 128; s > 0; s >>= 1) {
        if (tid < s) red[tid] = fmaxf(red[tid], red[tid + s]);
        __syncthreads();
    }
    float mx = red[0];
    float inv = (mx > 0.f) ? 16256.0f / mx : 0.0f;

    uint32_t* qh = (uint32_t*)g_qA2hi;
    uint32_t* ql = (uint32_t*)g_qA2lo;
    size_t base = (size_t)row * (Fd / 4);
#pragma unroll
    for (int j = 0; j < 4; j++) {
        int h0, l0, h1, l1, h2, l2, h3, l3;
        qsplit(v[j].x, inv, h0, l0); qsplit(v[j].y, inv, h1, l1);
        qsplit(v[j].z, inv, h2, l2); qsplit(v[j].w, inv, h3, l3);
        qh[base + tid + 256 * j] = pack4(h0, h1, h2, h3);
        ql[base + tid + 256 * j] = pack4(l0, l1, l2, l3);
    }
    if (tid == 0) g_sA2[row] = mx * (1.0f / 16256.0f);
}

// ---------------------------------------------------------------------------
// Weight quant, pass 1: per-column max -> scale.  grid (N/128, E), 256 thr.
// ---------------------------------------------------------------------------
template <int K, int N>
__global__ void wquant_scale(const float* __restrict__ W, float* __restrict__ sB) {
    int e = blockIdx.y;
    int col = threadIdx.x & 127;
    int half = threadIdx.x >> 7;
    int n = blockIdx.x * 128 + col;
    const float* Wb = W + (size_t)e * K * N;
    float m = 0.f;
    for (int k = half * (K / 2); k < (half + 1) * (K / 2); k++)
        m = fmaxf(m, fabsf(Wb[(size_t)k * N + n]));
    __shared__ float red[256];
    red[threadIdx.x] = m; __syncthreads();
    if (half == 0)
        sB[e * N + n] = fmaxf(red[threadIdx.x], red[threadIdx.x + 128]) * (1.0f / 16256.0f);
}

// ---------------------------------------------------------------------------
// Weight quant, pass 2: quantize + transpose to [e][n][k] planes.
// grid (N/128, K/KSLICE, E), 256 thr.
// ---------------------------------------------------------------------------
template <int K, int N, int KSLICE>
__global__ void wquant_pack(const float* __restrict__ W, const float* __restrict__ sB,
                            uint4* __restrict__ qhi4, uint4* __restrict__ qlo4) {
    int e = blockIdx.z;
    int nb = blockIdx.x * 128;
    int kbase = blockIdx.y * KSLICE;
    int col = threadIdx.x & 127;
    int kj = threadIdx.x >> 7;

    __shared__ float sinv[128];
    __shared__ __align__(16) int8_t th[128][48];
    __shared__ __align__(16) int8_t tl[128][48];

    if (threadIdx.x < 128) {
        float u = sB[e * N + nb + col];
        sinv[col] = (u > 0.f) ? 1.0f / u : 0.0f;
    }
    __syncthreads();

    const float* Wb = W + (size_t)e * K * N;
    int8_t* qhi = (int8_t*)qhi4;
    int8_t* qlo = (int8_t*)qlo4;

    for (int c = 0; c < KSLICE; c += 32) {
        int kc = kbase + c + kj * 16;
        float inv = sinv[col];
#pragma unroll
        for (int j = 0; j < 16; j++) {
            float v = Wb[(size_t)(kc + j) * N + nb + col];
            int hi, lo;
            qsplit(v, inv, hi, lo);
            th[col][kj * 16 + j] = (int8_t)hi;
            tl[col][kj * 16 + j] = (int8_t)lo;
        }
        __syncthreads();
        int rr = threadIdx.x >> 1, hh = threadIdx.x & 1;
        size_t off = ((size_t)e * N + nb + rr) * K + kbase + c + hh * 16;
        *(uint4*)(qhi + off) = *(const uint4*)&th[rr][hh * 16];
        *(uint4*)(qlo + off) = *(const uint4*)&tl[rr][hh * 16];
        __syncthreads();
    }
}

// ---------------------------------------------------------------------------
// int8 split IMMA GEMM.
//   C[e][512 x Ntot] = (A planes) @ (B planes)^T with rank-1 scales.
//   BM=128 BN=128 BK=32, 512 threads (16 warps, 4x4), warp tile 32x32.
//   All operands via cp.async (pre-transposed int8, K-major).
//   Per iter per warp: 8 ldmatrix.x4 + 24 IMMA (2 acc sets, RAW distance 4).
// SMEM stage: [Ahi][Alo][Bhi][Blo] each 128 rows x 48B = 24576 B; 3 stages.
// ---------------------------------------------------------------------------
#define STAGE_BYTES 24576
#define PLANE_BYTES 6144
#define GEMM_SMEM_BYTES (3 * STAGE_BYTES)   // 73728

template <int Kdim, int Ntot, bool DoGelu>
__global__ __launch_bounds__(512, 1)
void gemm_imma(const uint4* __restrict__ Ahi4, const uint4* __restrict__ Alo4,
               const float* __restrict__ sA,
               const uint4* __restrict__ Bhi4, const uint4* __restrict__ Blo4,
               const float* __restrict__ sB,
               const float* __restrict__ bias_, float* __restrict__ C_) {
    constexpr int NK = Kdim / 32;
    extern __shared__ int8_t smem[];
    const uint32_t sbase = smem_u32(smem);

    const int e  = blockIdx.z;
    const int m0 = blockIdx.y * 128;
    const int n0 = blockIdx.x * 128;
    const int tid = threadIdx.x;

    const int8_t* Ah = (const int8_t*)Ahi4 + ((size_t)e * Td + m0) * Kdim;
    const int8_t* Al = (const int8_t*)Alo4 + ((size_t)e * Td + m0) * Kdim;
    const int8_t* Bh = (const int8_t*)Bhi4 + ((size_t)e * Ntot + n0) * Kdim;
    const int8_t* Bl = (const int8_t*)Blo4 + ((size_t)e * Ntot + n0) * Kdim;

    // loader: 512 threads -> 1 A-chunk + 1 B-chunk each per stage
    const int lrow   = tid >> 2;          // 0..127
    const int lplane = (tid >> 1) & 1;    // 0 = hi, 1 = lo
    const int lhalf  = tid & 1;           // 16B half
    const int8_t* srcA = (lplane ? Al : Ah) + (size_t)lrow * Kdim + lhalf * 16;
    const int8_t* srcB = (lplane ? Bl : Bh) + (size_t)lrow * Kdim + lhalf * 16;
    const uint32_t dA = (uint32_t)(lplane * PLANE_BYTES + lrow * 48 + lhalf * 16);
    const uint32_t dB = dA + 2 * PLANE_BYTES;

    auto cpStage = [&](int i) {
        uint32_t sb = sbase + (uint32_t)((i % 3) * STAGE_BYTES);
        cp_async16(sb + dA, srcA + i * 32);
        cp_async16(sb + dB, srcB + i * 32);
        cp_commit();
    };

    // warp/fragment mapping
    const int wid  = tid >> 5;
    const int lane = tid & 31;
    const int wm = wid >> 2;              // 0..3
    const int wn = wid & 3;               // 0..3
    const int grp = lane >> 2;            // 0..7
    const int tg  = lane & 3;             // 0..3

    // ldmatrix lane address offsets (within a stage)
    const uint32_t aOff = (uint32_t)((wm * 32 + (lane & 15)) * 48 + ((lane >> 4) << 4));
    const uint32_t bOff = (uint32_t)(2 * PLANE_BYTES +
                          (wn * 32 + (lane & 15)) * 48 + ((lane >> 4) << 4));

    int acc1[2][4][4], acc2[2][4][4];
#pragma unroll
    for (int mt = 0; mt < 2; mt++)
#pragma unroll
        for (int nt = 0; nt < 4; nt++)
#pragma unroll
            for (int q = 0; q < 4; q++) { acc1[mt][nt][q] = 0; acc2[mt][nt][q] = 0; }

    cpStage(0);
    cpStage(1);

    for (int i = 0; i < NK; i++) {
        cp_wait1();
        __syncthreads();
        if (i + 2 < NK) cpStage(i + 2); else cp_commit();

        const uint32_t st = sbase + (uint32_t)((i % 3) * STAGE_BYTES);

        uint32_t ah[2][4], al[2][4], bh[4][2], bl[4][2];
        // A: plane x mt (rows wm*32 + mt*16 + r, canonical a0..a3 order)
#pragma unroll
        for (int mt = 0; mt < 2; mt++) {
            uint32_t base = st + aOff + (uint32_t)(mt * 16 * 48);
            ldsm_x4(ah[mt][0], ah[mt][1], ah[mt][2], ah[mt][3], base);
            ldsm_x4(al[mt][0], al[mt][1], al[mt][2], al[mt][3], base + PLANE_BYTES);
        }
        // B: plane x q (16 n-rows -> nt pair); m0,m1,m2,m3 = (b0 of 2q),(b0 of 2q+1),(b1 of 2q),(b1 of 2q+1)
#pragma unroll
        for (int q = 0; q < 2; q++) {
            uint32_t base = st + bOff + (uint32_t)(q * 16 * 48);
            ldsm_x4(bh[2 * q][0], bh[2 * q + 1][0], bh[2 * q][1], bh[2 * q + 1][1], base);
            ldsm_x4(bl[2 * q][0], bl[2 * q + 1][0], bl[2 * q][1], bl[2 * q + 1][1],
                    base + PLANE_BYTES);
        }

#pragma unroll
        for (int mt = 0; mt < 2; mt++) {
#pragma unroll
            for (int nt = 0; nt < 4; nt++)
                imma(acc1[mt][nt], ah[mt][0], ah[mt][1], ah[mt][2], ah[mt][3],
                     bh[nt][0], bh[nt][1]);
#pragma unroll
            for (int nt = 0; nt < 4; nt++)
                imma(acc2[mt][nt], ah[mt][0], ah[mt][1], ah[mt][2], ah[mt][3],
                     bl[nt][0], bl[nt][1]);
#pragma unroll
            for (int nt = 0; nt < 4; nt++)
                imma(acc2[mt][nt], al[mt][0], al[mt][1], al[mt][2], al[mt][3],
                     bh[nt][0], bh[nt][1]);
        }
    }

    // Epilogue: rank-1 scales + bias (+GELU), float2 stores
    float* C = C_ + (size_t)e * Td * Ntot;
#pragma unroll
    for (int mt = 0; mt < 2; mt++) {
        int r0 = m0 + wm * 32 + mt * 16 + grp;
        float uA0 = sA[e * Td + r0];
        float uA1 = sA[e * Td + r0 + 8];
#pragma unroll
        for (int nt = 0; nt < 4; nt++) {
            int col = n0 + wn * 32 + nt * 8 + tg * 2;
            float uB0 = sB[e * Ntot + col];
            float uB1 = sB[e * Ntot + col + 1];
            float bv0 = bias_[(size_t)e * Ntot + col];
            float bv1 = bias_[(size_t)e * Ntot + col + 1];
            float2 v0, v1;
            v0.x = (16384.f * (float)acc1[mt][nt][0] + 128.f * (float)acc2[mt][nt][0]) * uA0 * uB0 + bv0;
            v0.y = (16384.f * (float)acc1[mt][nt][1] + 128.f * (float)acc2[mt][nt][1]) * uA0 * uB1 + bv1;
            v1.x = (16384.f * (float)acc1[mt][nt][2] + 128.f * (float)acc2[mt][nt][2]) * uA1 * uB0 + bv0;
            v1.y = (16384.f * (float)acc1[mt][nt][3] + 128.f * (float)acc2[mt][nt][3]) * uA1 * uB1 + bv1;
            if (DoGelu) {
                v0.x = gelu_exact(v0.x); v0.y = gelu_exact(v0.y);
                v1.x = gelu_exact(v1.x); v1.y = gelu_exact(v1.y);
            }
            *(float2*)(C + (size_t)r0 * Ntot + col) = v0;
            *(float2*)(C + (size_t)(r0 + 8) * Ntot + col) = v1;
        }
    }
}

// ---------------------------------------------------------------------------
// Combine (unchanged)
// ---------------------------------------------------------------------------
__global__ void combine_kernel(float* __restrict__ out) {
    int m = blockIdx.x;
    int t = m >> 2;
    int q = m & 3;
    int e1 = g_order[t][2 * q];
    int e2 = g_order[t][2 * q + 1];
    const float4* o1 = (const float4*)(g_obuf + ((size_t)e1 * Td + t) * Hd);
    const float4* o2 = (const float4*)(g_obuf + ((size_t)e2 * Td + t) * Hd);
    float4* dst = (float4*)(out + (size_t)m * Hd);
    float4 a = o1[threadIdx.x];
    float4 b = o2[threadIdx.x];
    float4 v; v.x = a.x + b.x; v.y = a.y + b.y; v.z = a.z + b.z; v.w = a.w + b.w;
    dst[threadIdx.x] = v;
}

// ---------------------------------------------------------------------------
extern "C" void kernel_launch(void* const* d_in, const int* in_sizes, int n_in,
                              void* d_out, int out_size) {
    (void)in_sizes; (void)n_in;
    const float* x  = (const float*)d_in[0];
    const float* Wg = (const float*)d_in[1];
    const float* bg = (const float*)d_in[2];
    const float* W1 = (const float*)d_in[3];
    const float* b1 = (const float*)d_in[4];
    const float* W2 = (const float*)d_in[5];
    const float* b2 = (const float*)d_in[6];
    float* out = (float*)d_out;

    uint4 *qa1h, *qa1l, *qa2h, *qa2l, *w1h, *w1l, *w2h, *w2l;
    float *sa1, *sa2, *sb1, *sb2, *hmid, *obuf;
    cudaGetSymbolAddress((void**)&qa1h, g_qA1hi);
    cudaGetSymbolAddress((void**)&qa1l, g_qA1lo);
    cudaGetSymbolAddress((void**)&qa2h, g_qA2hi);
    cudaGetSymbolAddress((void**)&qa2l, g_qA2lo);
    cudaGetSymbolAddress((void**)&w1h,  g_W1q_hi);
    cudaGetSymbolAddress((void**)&w1l,  g_W1q_lo);
    cudaGetSymbolAddress((void**)&w2h,  g_W2q_hi);
    cudaGetSymbolAddress((void**)&w2l,  g_W2q_lo);
    cudaGetSymbolAddress((void**)&sa1,  g_sA1);
    cudaGetSymbolAddress((void**)&sa2,  g_sA2);
    cudaGetSymbolAddress((void**)&sb1,  g_sB1);
    cudaGetSymbolAddress((void**)&sb2,  g_sB2);
    cudaGetSymbolAddress((void**)&hmid, g_hmid);
    cudaGetSymbolAddress((void**)&obuf, g_obuf);

    cudaFuncSetAttribute(gemm_imma<Hd, Fd, true>,
                         cudaFuncAttributeMaxDynamicSharedMemorySize, GEMM_SMEM_BYTES);
    cudaFuncSetAttribute(gemm_imma<Fd, Hd, false>,
                         cudaFuncAttributeMaxDynamicSharedMemorySize, GEMM_SMEM_BYTES);

    // Output tail (batches 1-3 + aux-loss scalar, all exactly zero)
    size_t nz = (size_t)OUT_TOK * Hd;
    cudaMemsetAsync(out + nz, 0, ((size_t)out_size - nz) * sizeof(float), 0);

    gate_kernel<<<Td / 8, 256>>>(x, Wg, bg);
    dispatch_kernel<<<dim3(Td, Ed), 256>>>(x);

    // Weight quantization (per-column scales; transpose to [e][n][k] planes)
    wquant_scale<Hd, Fd><<<dim3(Fd / 128, Ed), 256>>>(W1, sb1);
    wquant_pack<Hd, Fd, Hd><<<dim3(Fd / 128, 1, Ed), 256>>>(W1, sb1, w1h, w1l);
    wquant_scale<Fd, Hd><<<dim3(Hd / 128, Ed), 256>>>(W2, sb2);
    wquant_pack<Fd, Hd, 1024><<<dim3(Hd / 128, Fd / 1024, Ed), 256>>>(W2, sb2, w2h, w2l);

    // GEMM1 + GELU: (512 x 1024) @ (1024 x 4096) per expert, int8 split
    gemm_imma<Hd, Fd, true><<<dim3(Fd / 128, Td / 128, Ed), 512, GEMM_SMEM_BYTES>>>(
        qa1h, qa1l, sa1, w1h, w1l, sb1, b1, hmid);

    hquant_kernel<<<Ed * Td, 256>>>();

    // GEMM2: (512 x 4096) @ (4096 x 1024) per expert, int8 split
    gemm_imma<Fd, Hd, false><<<dim3(Hd / 128, Td / 128, Ed), 512, GEMM_SMEM_BYTES>>>(
        qa2h, qa2l, sa2, w2h, w2l, sb2, b2, obuf);

    combine_kernel<<<OUT_TOK, 256>>>(out);
}

// round 17
// speedup vs baseline: 3.0801x; 3.0801x over previous
#include <cuda_runtime.h>
#include <math.h>
#include <stdint.h>

// ---------------------------------------------------------------------------
// Shapes (fixed)
// ---------------------------------------------------------------------------
#define Hd 1024
#define Fd 4096
#define Ed 8
#define Td 512
#define OUT_TOK 2048

// ---------------------------------------------------------------------------
// Static device scratch (allocation-free per harness rules)
// ---------------------------------------------------------------------------
__device__ float g_buf [Ed * Td * Hd];                  // dispatched acts (tf32-rounded)
__device__ float g_hmid[(size_t)Ed * Td * Fd];          // GEMM1+GELU out (tf32-rounded)
__device__ float g_obuf[Ed * Td * Hd];                  // GEMM2 out (fp32)
__device__ int   g_order[Td][Ed];
__device__ float g_score[Td][Ed];
__device__ int   g_tileCtr[2];                          // persistent-GEMM tile counters

// ---------------------------------------------------------------------------
// Helpers
// ---------------------------------------------------------------------------
__device__ __forceinline__ uint32_t smem_u32(const void* p) {
    uint32_t a;
    asm("{ .reg .u64 t; cvta.to.shared.u64 t, %1; cvt.u32.u64 %0, t; }" : "=r"(a) : "l"(p));
    return a;
}
__device__ __forceinline__ float tf32r(float x) {
    uint32_t u;
    asm("cvt.rna.tf32.f32 %0, %1;" : "=r"(u) : "f"(x));
    return __uint_as_float(u);
}
__device__ __forceinline__ void cp_async16(uint32_t saddr, const void* gaddr) {
    asm volatile("cp.async.cg.shared.global [%0], [%1], 16;" :: "r"(saddr), "l"(gaddr));
}
__device__ __forceinline__ void cp_commit() {
    asm volatile("cp.async.commit_group;" ::: "memory");
}
__device__ __forceinline__ void cp_wait1() {
    asm volatile("cp.async.wait_group 1;" ::: "memory");
}
__device__ __forceinline__ void ldsm_x4(uint32_t& r0, uint32_t& r1, uint32_t& r2,
                                        uint32_t& r3, uint32_t addr) {
    asm volatile("ldmatrix.sync.aligned.m8n8.x4.shared.b16 {%0,%1,%2,%3}, [%4];"
                 : "=r"(r0), "=r"(r1), "=r"(r2), "=r"(r3) : "r"(addr));
}
__device__ __forceinline__ void mma_tf32(float c[4], uint32_t a0, uint32_t a1,
                                         uint32_t a2, uint32_t a3,
                                         uint32_t b0, uint32_t b1) {
    asm volatile(
        "mma.sync.aligned.m16n8k8.row.col.f32.tf32.tf32.f32 "
        "{%0,%1,%2,%3}, {%4,%5,%6,%7}, {%8,%9}, {%0,%1,%2,%3};"
        : "+f"(c[0]), "+f"(c[1]), "+f"(c[2]), "+f"(c[3])
        : "r"(a0), "r"(a1), "r"(a2), "r"(a3), "r"(b0), "r"(b1));
}
__device__ __forceinline__ float gelu_exact(float v) {
    return 0.5f * v * (1.0f + erff(v * 0.70710678118654752f));
}

// ---------------------------------------------------------------------------
// Gating
// ---------------------------------------------------------------------------
__global__ void gate_kernel(const float* __restrict__ x,
                            const float* __restrict__ Wg,
                            const float* __restrict__ bg) {
    int warp = threadIdx.x >> 5;
    int lane = threadIdx.x & 31;
    int t = blockIdx.x * 8 + warp;
    if (t >= Td) return;

    const float* xr = x + (size_t)t * Hd;
    float acc[Ed];
#pragma unroll
    for (int e = 0; e < Ed; e++) acc[e] = 0.f;
    for (int h = lane; h < Hd; h += 32) {
        float xv = xr[h];
        const float* wr = Wg + (size_t)h * Ed;
#pragma unroll
        for (int e = 0; e < Ed; e++) acc[e] += xv * wr[e];
    }
#pragma unroll
    for (int e = 0; e < Ed; e++) {
#pragma unroll
        for (int o = 16; o > 0; o >>= 1)
            acc[e] += __shfl_xor_sync(0xffffffffu, acc[e], o);
    }
    if (lane == 0) {
        float l[Ed], p[Ed];
        float mx = -1e30f;
#pragma unroll
        for (int e = 0; e < Ed; e++) { l[e] = acc[e] + bg[e]; mx = fmaxf(mx, l[e]); }
        float s = 0.f;
#pragma unroll
        for (int e = 0; e < Ed; e++) { p[e] = expf(l[e] - mx); s += p[e]; }
#pragma unroll
        for (int e = 0; e < Ed; e++) p[e] /= s;
        float sum = 0.f;
#pragma unroll
        for (int e = 0; e < Ed; e++) sum += p[e];
        float inv = 1.0f / (sum + 1e-9f);
        bool used[Ed];
#pragma unroll
        for (int e = 0; e < Ed; e++) used[e] = false;
        for (int r = 0; r < Ed; r++) {
            int best = -1; float bv = -1e30f;
            for (int e = 0; e < Ed; e++)
                if (!used[e] && p[e] > bv) { bv = p[e]; best = e; }
            used[best] = true;
            g_order[t][r] = best;
            g_score[t][r] = bv * inv;
        }
    }
}

// ---------------------------------------------------------------------------
// Dispatch (tf32-rounds the MMA A operand)
// ---------------------------------------------------------------------------
__global__ void dispatch_kernel(const float* __restrict__ x) {
    int t = blockIdx.x;
    int r = blockIdx.y;
    int e = g_order[t][r];
    float sc = g_score[t][r];
    int src = 4 * t + (r >> 1);
    const float4* xs = (const float4*)(x + (size_t)src * Hd);
    float4* dst = (float4*)(g_buf + ((size_t)e * Td + t) * Hd);
    float4 v = xs[threadIdx.x];
    v.x = tf32r(v.x * sc); v.y = tf32r(v.y * sc);
    v.z = tf32r(v.z * sc); v.w = tf32r(v.w * sc);
    dst[threadIdx.x] = v;
}

// ---------------------------------------------------------------------------
// tf32 mma.sync GEMM (R10 mainloop) + PERSISTENT atomic tile scheduler.
//   BM=128 BN=128 BK=16, 256 threads, 2 CTAs/SM, grid = 296 flat CTAs.
//   Tiles stolen via atomicAdd; per-tile math identical to R10 ->
//   deterministic output independent of steal order.
//   A: 3-stage cp.async. B: LDG->reg->STS transpose (stride-20 layout).
//   Fragments via ldmatrix.x4 (4 A-ops + 2 B-ops per kk).
// ---------------------------------------------------------------------------
#define LDSSTR 20
#define TILE_WORDS (128 * LDSSTR)          // per-operand per-stage words
#define GEMM_SMEM_BYTES (2 * 3 * TILE_WORDS * 4)   // 61440
#define PERSIST_GRID 296

template <int Kdim, int Ndim, bool DoGelu>
__global__ __launch_bounds__(256, 2)
void gemm_mma(const float* __restrict__ A_, const float* __restrict__ B_,
              const float* __restrict__ bias_, float* __restrict__ C_,
              int* __restrict__ tileCtr) {
    constexpr int BK = 16;
    constexpr int NK = Kdim / BK;
    constexpr int NT_N = Ndim / 128;       // n-tiles (32 or 8, pow2)
    constexpr int NTILES = NT_N * (Td / 128) * Ed;

    extern __shared__ float smem[];
    float* AsBase = smem;                       // [3][128 row][20]
    float* BsBase = smem + 3 * TILE_WORDS;      // [3][128 n][20 k]
    __shared__ int s_tile;

    const int tid = threadIdx.x;

    // ---- tile-independent thread mappings ----
    const int lrow = tid >> 1;                  // A loader: 0..127
    const int lcol = (tid & 1) * 8;             // 0 or 8
    const uint32_t sA0 = smem_u32(AsBase) + (uint32_t)(lrow * LDSSTR + lcol) * 4;

    const int n_b = tid & 127;                  // B loader
    const int kq  = tid >> 7;                   // 0..1
    float br[8];

    const int wid = tid >> 5;
    const int lane = tid & 31;
    const int wm = wid >> 2;                    // 0..1
    const int wn = wid & 3;                     // 0..3
    const int grp = lane >> 2;                  // 0..7
    const int tg  = lane & 3;                   // 0..3

    const uint32_t aLdsmBase = smem_u32(AsBase) +
        (uint32_t)(((wm * 64 + (lane & 15)) * LDSSTR + ((lane >> 4) << 2)) * 4);
    const uint32_t bLdsmBase = smem_u32(BsBase) +
        (uint32_t)(((wn * 32 + ((lane >> 4) << 3) + (lane & 7)) * LDSSTR +
                    (((lane >> 3) & 1) << 2)) * 4);

    for (;;) {
        __syncthreads();                        // SMEM stages free of old readers
        if (tid == 0) s_tile = atomicAdd(tileCtr, 1);
        __syncthreads();
        const int tile = s_tile;
        if (tile >= NTILES) break;

        // decode: consecutive tiles share (e, nTile) across m -> B tile L2 reuse
        const int mTile = tile & 3;                       // Td/128 = 4
        const int rest  = tile >> 2;
        const int nTile = rest & (NT_N - 1);
        const int e     = rest >> (NT_N == 32 ? 5 : 3);

        const int m0 = mTile * 128;
        const int n0 = nTile * 128;

        const float* gA0 = A_ + (size_t)e * Td * Kdim + (size_t)(m0 + lrow) * Kdim + lcol;
        const float* gB0 = B_ + (size_t)e * Kdim * Ndim + (size_t)(kq * 4) * Ndim + n0 + n_b;

        auto cpA = [&](int i) {
            uint32_t sa = sA0 + (uint32_t)((i % 3) * TILE_WORDS) * 4;
            const float* ga = gA0 + i * BK;
            cp_async16(sa, ga);
            cp_async16(sa + 16, ga + 4);
            cp_commit();
        };
        auto ldgB = [&](int i) {
            const float* p = gB0 + (size_t)(i * BK) * Ndim;
#pragma unroll
            for (int ii = 0; ii < 4; ii++) br[ii] = tf32r(p[(size_t)ii * Ndim]);
            const float* p2 = p + (size_t)8 * Ndim;
#pragma unroll
            for (int ii = 0; ii < 4; ii++) br[4 + ii] = tf32r(p2[(size_t)ii * Ndim]);
        };
        auto stsB = [&](int i) {
            float* bs = BsBase + (i % 3) * TILE_WORDS + n_b * LDSSTR + kq * 4;
            *(float4*)(bs)     = *(const float4*)&br[0];
            *(float4*)(bs + 8) = *(const float4*)&br[4];
        };

        float c[4][4][4];
#pragma unroll
        for (int mt = 0; mt < 4; mt++)
#pragma unroll
            for (int nt = 0; nt < 4; nt++)
#pragma unroll
                for (int q = 0; q < 4; q++) c[mt][nt][q] = 0.f;

        // prologue: stages 0 and 1
        ldgB(0); stsB(0);
        ldgB(1); stsB(1);
        cpA(0);  cpA(1);

        for (int i = 0; i < NK; i++) {
            cp_wait1();
            __syncthreads();
            if (i + 2 < NK) { ldgB(i + 2); cpA(i + 2); }
            else cp_commit();

            const uint32_t stA = aLdsmBase + (uint32_t)((i % 3) * TILE_WORDS) * 4;
            const uint32_t stB = bLdsmBase + (uint32_t)((i % 3) * TILE_WORDS) * 4;

#pragma unroll
            for (int kk = 0; kk < 2; kk++) {
                const uint32_t koff = (uint32_t)(kk * 8) * 4;
                uint32_t a[4][4], b[4][2];
#pragma unroll
                for (int q = 0; q < 2; q++) {
                    uint32_t addr = stB + koff + (uint32_t)(q * 16 * LDSSTR) * 4;
                    ldsm_x4(b[2 * q][0], b[2 * q][1], b[2 * q + 1][0], b[2 * q + 1][1], addr);
                }
#pragma unroll
                for (int mt = 0; mt < 4; mt++) {
                    uint32_t addr = stA + koff + (uint32_t)(mt * 16 * LDSSTR) * 4;
                    ldsm_x4(a[mt][0], a[mt][1], a[mt][2], a[mt][3], addr);
                }
#pragma unroll
                for (int mt = 0; mt < 4; mt++)
#pragma unroll
                    for (int nt = 0; nt < 4; nt++)
                        mma_tf32(c[mt][nt], a[mt][0], a[mt][1], a[mt][2], a[mt][3],
                                 b[nt][0], b[nt][1]);
            }

            if (i + 2 < NK) stsB(i + 2);   // next-iter barrier protects readers
        }

        // Epilogue: bias (+GELU +tf32 round), float2 stores (no SMEM use)
        const float* bias = bias_ + (size_t)e * Ndim + n0;
        float* C = C_ + (size_t)e * Td * Ndim;
#pragma unroll
        for (int mt = 0; mt < 4; mt++) {
            int r0 = m0 + wm * 64 + mt * 16 + grp;
#pragma unroll
            for (int nt = 0; nt < 4; nt++) {
                int col = wn * 32 + nt * 8 + tg * 2;
                float bx = bias[col], by = bias[col + 1];
                float2 v0, v1;
                v0.x = c[mt][nt][0] + bx;  v0.y = c[mt][nt][1] + by;
                v1.x = c[mt][nt][2] + bx;  v1.y = c[mt][nt][3] + by;
                if (DoGelu) {
                    v0.x = tf32r(gelu_exact(v0.x)); v0.y = tf32r(gelu_exact(v0.y));
                    v1.x = tf32r(gelu_exact(v1.x)); v1.y = tf32r(gelu_exact(v1.y));
                }
                *(float2*)(C + (size_t)r0 * Ndim + n0 + col) = v0;
                *(float2*)(C + (size_t)(r0 + 8) * Ndim + n0 + col) = v1;
            }
        }
    }
}

// ---------------------------------------------------------------------------
// Combine
// ---------------------------------------------------------------------------
__global__ void combine_kernel(float* __restrict__ out) {
    int m = blockIdx.x;
    int t = m >> 2;
    int q = m & 3;
    int e1 = g_order[t][2 * q];
    int e2 = g_order[t][2 * q + 1];
    const float4* o1 = (const float4*)(g_obuf + ((size_t)e1 * Td + t) * Hd);
    const float4* o2 = (const float4*)(g_obuf + ((size_t)e2 * Td + t) * Hd);
    float4* dst = (float4*)(out + (size_t)m * Hd);
    float4 a = o1[threadIdx.x];
    float4 b = o2[threadIdx.x];
    float4 v; v.x = a.x + b.x; v.y = a.y + b.y; v.z = a.z + b.z; v.w = a.w + b.w;
    dst[threadIdx.x] = v;
}

// ---------------------------------------------------------------------------
extern "C" void kernel_launch(void* const* d_in, const int* in_sizes, int n_in,
                              void* d_out, int out_size) {
    (void)in_sizes; (void)n_in;
    const float* x  = (const float*)d_in[0];
    const float* Wg = (const float*)d_in[1];
    const float* bg = (const float*)d_in[2];
    const float* W1 = (const float*)d_in[3];
    const float* b1 = (const float*)d_in[4];
    const float* W2 = (const float*)d_in[5];
    const float* b2 = (const float*)d_in[6];
    float* out = (float*)d_out;

    float *buf, *hmid, *obuf;
    int* ctr;
    cudaGetSymbolAddress((void**)&buf,  g_buf);
    cudaGetSymbolAddress((void**)&hmid, g_hmid);
    cudaGetSymbolAddress((void**)&obuf, g_obuf);
    cudaGetSymbolAddress((void**)&ctr,  g_tileCtr);

    cudaFuncSetAttribute(gemm_mma<Hd, Fd, true>,
                         cudaFuncAttributeMaxDynamicSharedMemorySize, GEMM_SMEM_BYTES);
    cudaFuncSetAttribute(gemm_mma<Fd, Hd, false>,
                         cudaFuncAttributeMaxDynamicSharedMemorySize, GEMM_SMEM_BYTES);

    // Reset persistent tile counters (captured in the graph -> every replay)
    cudaMemsetAsync(ctr, 0, 2 * sizeof(int), 0);

    // Output tail (batches 1-3 + aux-loss scalar, all exactly zero)
    size_t nz = (size_t)OUT_TOK * Hd;
    cudaMemsetAsync(out + nz, 0, ((size_t)out_size - nz) * sizeof(float), 0);

    gate_kernel<<<Td / 8, 256>>>(x, Wg, bg);
    dispatch_kernel<<<dim3(Td, Ed), 256>>>(x);

    // GEMM1 + GELU: per expert (512 x 1024) @ (1024 x 4096), persistent
    gemm_mma<Hd, Fd, true><<<PERSIST_GRID, 256, GEMM_SMEM_BYTES>>>(buf, W1, b1, hmid, ctr);
    // GEMM2: per expert (512 x 4096) @ (4096 x 1024), persistent
    gemm_mma<Fd, Hd, false><<<PERSIST_GRID, 256, GEMM_SMEM_BYTES>>>(hmid, W2, b2, obuf, ctr + 1);

    combine_kernel<<<OUT_TOK, 256>>>(out);
}